// round 1
// baseline (speedup 1.0000x reference)
#include <cuda_runtime.h>

// Neural ODE: dh/dt = W2 @ tanh(W1 @ h + b1) + b2, h in R^2, hidden=50.
// Reference solves with dopri5 @ rtol=1e-7; we need rel_err < 1e-3, so a
// fixed-step RK4 with 4 substeps per output interval is more than enough.
//
// Parallelization: one warp per batch element (1024 warps, all resident in
// one wave on 148 SMs). Each lane owns hidden units {lane, lane+32} with all
// its weights in registers; the length-50 dot products for the 2 outputs are
// reduced with a 5-round shfl_xor butterfly. Fully latency-bound by design.

#define FULLMASK 0xFFFFFFFFu
#define SUBSTEPS 4

// Accurate-enough tanh independent of compiler fast-math flags.
// __expf: few-ulp; __fdividef: ~2 ulp => ~1e-7 relative error overall.
__device__ __forceinline__ float my_tanh(float x) {
    float ax = fabsf(x);
    float e  = __expf(-2.0f * ax);
    float t  = __fdividef(1.0f - e, 1.0f + e);
    return copysignf(t, x);
}

__global__ void __launch_bounds__(128, 8)
ode_rk4_kernel(const float* __restrict__ h0,
               const float* __restrict__ tarr,
               const float* __restrict__ w1,   // [50,2] row-major
               const float* __restrict__ b1,   // [50]
               const float* __restrict__ w2,   // [2,50] row-major
               const float* __restrict__ b2,   // [2]
               float* __restrict__ out,        // [nt, batch, 2]
               int nt, int batch)
{
    const int warp = (blockIdx.x * blockDim.x + threadIdx.x) >> 5;
    const int lane = threadIdx.x & 31;
    if (warp >= batch) return;

    // Per-lane hidden units: u0 = lane, u1 = lane + 32 (valid iff lane < 18).
    const int u0 = lane;
    const int u1 = lane + 32;
    const bool v1 = (u1 < 50);

    const float w1a0 = w1[2 * u0];
    const float w1b0 = w1[2 * u0 + 1];
    const float bh0  = b1[u0];
    const float w2a0 = w2[u0];
    const float w2b0 = w2[50 + u0];

    const float w1a1 = v1 ? w1[2 * u1]     : 0.0f;
    const float w1b1 = v1 ? w1[2 * u1 + 1] : 0.0f;
    const float bh1  = v1 ? b1[u1]         : 0.0f;
    const float w2a1 = v1 ? w2[u1]         : 0.0f;
    const float w2b1 = v1 ? w2[50 + u1]    : 0.0f;

    const float bias0 = b2[0];
    const float bias1 = b2[1];

    float hx = h0[2 * warp];
    float hy = h0[2 * warp + 1];

    // t = 0 row is the initial state exactly (reference concatenates y0).
    if (lane == 0) {
        *reinterpret_cast<float2*>(out + 2 * warp) = make_float2(hx, hy);
    }

    // Vector-field eval: all lanes end with the full (fx, fy).
    auto evalf = [&](float x, float y, float& fx, float& fy) {
        float z0 = my_tanh(fmaf(w1a0, x, fmaf(w1b0, y, bh0)));
        float z1 = my_tanh(fmaf(w1a1, x, fmaf(w1b1, y, bh1)));
        float a0 = fmaf(w2a0, z0, w2a1 * z1);
        float a1 = fmaf(w2b0, z0, w2b1 * z1);
        #pragma unroll
        for (int off = 16; off; off >>= 1) {
            a0 += __shfl_xor_sync(FULLMASK, a0, off);
            a1 += __shfl_xor_sync(FULLMASK, a1, off);
        }
        fx = a0 + bias0;
        fy = a1 + bias1;
    };

    float tprev = __ldg(&tarr[0]);
    for (int i = 1; i < nt; ++i) {
        const float ti = __ldg(&tarr[i]);
        const float dt = (ti - tprev) * (1.0f / SUBSTEPS);
        tprev = ti;

        #pragma unroll
        for (int s = 0; s < SUBSTEPS; ++s) {
            float k1x, k1y, k2x, k2y, k3x, k3y, k4x, k4y;
            evalf(hx, hy, k1x, k1y);
            evalf(fmaf(0.5f * dt, k1x, hx), fmaf(0.5f * dt, k1y, hy), k2x, k2y);
            evalf(fmaf(0.5f * dt, k2x, hx), fmaf(0.5f * dt, k2y, hy), k3x, k3y);
            evalf(fmaf(dt, k3x, hx),        fmaf(dt, k3y, hy),        k4x, k4y);
            const float c = dt * (1.0f / 6.0f);
            hx += c * (k1x + 2.0f * (k2x + k3x) + k4x);
            hy += c * (k1y + 2.0f * (k2y + k3y) + k4y);
        }

        if (lane == 0) {
            *reinterpret_cast<float2*>(out + (size_t)i * 2 * batch + 2 * warp) =
                make_float2(hx, hy);
        }
    }
}

extern "C" void kernel_launch(void* const* d_in, const int* in_sizes, int n_in,
                              void* d_out, int out_size)
{
    const float* h0 = (const float*)d_in[0];
    const float* t  = (const float*)d_in[1];
    const float* w1 = (const float*)d_in[2];
    const float* b1 = (const float*)d_in[3];
    const float* w2 = (const float*)d_in[4];
    const float* b2 = (const float*)d_in[5];
    float* out = (float*)d_out;

    const int batch = in_sizes[0] / 2;   // 1024
    const int nt    = in_sizes[1];       // 100

    const int threads = 128;                       // 4 warps / block
    const int warps_per_block = threads / 32;
    const int grid = (batch + warps_per_block - 1) / warps_per_block;

    ode_rk4_kernel<<<grid, threads>>>(h0, t, w1, b1, w2, b2, out, nt, batch);
}

// round 2
// speedup vs baseline: 3.9353x; 3.9353x over previous
#include <cuda_runtime.h>

// Neural ODE: dh/dt = W2 @ tanh(W1 @ h + b1) + b2, h in R^2, hidden=50.
// Fixed-step RK4, ONE step per output interval (99 steps, 396 evals).
// Error model: 4-substep RK4 measured rel_err 5.5e-7; h^4 scaling gives
// ~1.4e-4 at 1 substep — 7x under the 1e-3 threshold.
//
// Parallelization: 16 lanes per batch element (2 elements per warp).
// Each lane owns up to 4 hidden units entirely in registers; the length-50
// dot products reduce in a 4-round shfl_xor butterfly confined to the
// 16-lane group. Pure critical-path-latency kernel by design.

#define FULLMASK 0xFFFFFFFFu

// Accurate tanh independent of compiler fast-math flags (~1e-7 rel).
__device__ __forceinline__ float my_tanh(float x) {
    float ax = fabsf(x);
    float e  = __expf(-2.0f * ax);
    float t  = __fdividef(1.0f - e, 1.0f + e);
    return copysignf(t, x);
}

__global__ void __launch_bounds__(128, 8)
ode_rk4_kernel(const float* __restrict__ h0,
               const float* __restrict__ tarr,
               const float* __restrict__ w1,   // [50,2] row-major
               const float* __restrict__ b1,   // [50]
               const float* __restrict__ w2,   // [2,50] row-major
               const float* __restrict__ b2,   // [2]
               float* __restrict__ out,        // [nt, batch, 2]
               int nt, int batch)
{
    const int warp  = (blockIdx.x * blockDim.x + threadIdx.x) >> 5;
    const int lane  = threadIdx.x & 31;
    const int grp   = lane >> 4;      // 0 or 1: which element of this warp
    const int glane = lane & 15;      // lane within the 16-lane group
    const int elem  = warp * 2 + grp;
    if (elem >= batch) return;

    // Each lane owns hidden units glane + 16*j, j = 0..3 (u<50 valid).
    float W1a[4], W1b[4], Bh[4], W2a[4], W2b[4];
    #pragma unroll
    for (int j = 0; j < 4; ++j) {
        const int u = glane + 16 * j;
        const bool v = (u < 50);
        W1a[j] = v ? w1[2 * u]     : 0.0f;
        W1b[j] = v ? w1[2 * u + 1] : 0.0f;
        Bh[j]  = v ? b1[u]         : 0.0f;
        W2a[j] = v ? w2[u]         : 0.0f;
        W2b[j] = v ? w2[50 + u]    : 0.0f;
    }
    const float bias0 = b2[0];
    const float bias1 = b2[1];

    float hx = h0[2 * elem];
    float hy = h0[2 * elem + 1];

    // t=0 row is the initial state exactly.
    if (glane == 0) {
        *reinterpret_cast<float2*>(out + 2 * elem) = make_float2(hx, hy);
    }

    // Vector-field eval: all 16 lanes of the group end with the full (fx, fy).
    auto evalf = [&](float x, float y, float& fx, float& fy) {
        float a0 = 0.0f, a1 = 0.0f;
        #pragma unroll
        for (int j = 0; j < 4; ++j) {
            float z = my_tanh(fmaf(W1a[j], x, fmaf(W1b[j], y, Bh[j])));
            a0 = fmaf(W2a[j], z, a0);
            a1 = fmaf(W2b[j], z, a1);
        }
        #pragma unroll
        for (int off = 8; off; off >>= 1) {   // 4 rounds, stays in 16-group
            a0 += __shfl_xor_sync(FULLMASK, a0, off);
            a1 += __shfl_xor_sync(FULLMASK, a1, off);
        }
        fx = a0 + bias0;
        fy = a1 + bias1;
    };

    float tprev = __ldg(&tarr[0]);
    for (int i = 1; i < nt; ++i) {
        const float ti = __ldg(&tarr[i]);
        const float dt = ti - tprev;
        tprev = ti;

        float k1x, k1y, k2x, k2y, k3x, k3y, k4x, k4y;
        evalf(hx, hy, k1x, k1y);
        evalf(fmaf(0.5f * dt, k1x, hx), fmaf(0.5f * dt, k1y, hy), k2x, k2y);
        evalf(fmaf(0.5f * dt, k2x, hx), fmaf(0.5f * dt, k2y, hy), k3x, k3y);
        evalf(fmaf(dt, k3x, hx),        fmaf(dt, k3y, hy),        k4x, k4y);
        const float c = dt * (1.0f / 6.0f);
        hx += c * (k1x + 2.0f * (k2x + k3x) + k4x);
        hy += c * (k1y + 2.0f * (k2y + k3y) + k4y);

        if (glane == 0) {
            *reinterpret_cast<float2*>(out + (size_t)i * 2 * batch + 2 * elem) =
                make_float2(hx, hy);
        }
    }
}

extern "C" void kernel_launch(void* const* d_in, const int* in_sizes, int n_in,
                              void* d_out, int out_size)
{
    const float* h0 = (const float*)d_in[0];
    const float* t  = (const float*)d_in[1];
    const float* w1 = (const float*)d_in[2];
    const float* b1 = (const float*)d_in[3];
    const float* w2 = (const float*)d_in[4];
    const float* b2 = (const float*)d_in[5];
    float* out = (float*)d_out;

    const int batch = in_sizes[0] / 2;   // 1024
    const int nt    = in_sizes[1];       // 100

    const int threads = 128;             // 4 warps = 8 elements per block
    const int elems_per_block = (threads / 32) * 2;
    const int grid = (batch + elems_per_block - 1) / elems_per_block;

    ode_rk4_kernel<<<grid, threads>>>(h0, t, w1, b1, w2, b2, out, nt, batch);
}

// round 3
// speedup vs baseline: 8.3170x; 2.1135x over previous
#include <cuda_runtime.h>

// Neural ODE: dh/dt = W2 @ tanh(W1 @ h + b1) + b2, h in R^2, hidden=50.
//
// Strategy: the kernel is pure sequential-latency (all pipes idle in ncu),
// so minimize the number of sequential vector-field evals.
//   - RK4 with ONE step per 4 output intervals (H ~ 0.081).
//   - Interior outputs via cubic Hermite dense output from (y0,f0,y1,f1).
//   - f1 is reused as the next step's k1 => 4 evals per 4 intervals.
// Total sequential evals: 1 + 4*ceil(99/4) = 101 (was 396).
//
// Parallelization: 16 lanes per batch element (2 elements/warp); each lane
// holds up to 4 hidden units' weights in registers; 4-round shfl_xor
// butterfly produces the 2-dim vector field in all lanes.

#define FULLMASK 0xFFFFFFFFu
#define CHUNK 4

// Accurate tanh independent of fast-math flags (~1e-7 rel).
__device__ __forceinline__ float my_tanh(float x) {
    float ax = fabsf(x);
    float e  = __expf(-2.0f * ax);
    float t  = __fdividef(1.0f - e, 1.0f + e);
    return copysignf(t, x);
}

__global__ void __launch_bounds__(128, 8)
ode_rk4_dense_kernel(const float* __restrict__ h0,
                     const float* __restrict__ tarr,
                     const float* __restrict__ w1,   // [50,2]
                     const float* __restrict__ b1,   // [50]
                     const float* __restrict__ w2,   // [2,50]
                     const float* __restrict__ b2,   // [2]
                     float* __restrict__ out,        // [nt, batch, 2]
                     int nt, int batch)
{
    const int warp  = (blockIdx.x * blockDim.x + threadIdx.x) >> 5;
    const int lane  = threadIdx.x & 31;
    const int grp   = lane >> 4;
    const int glane = lane & 15;
    const int elem  = warp * 2 + grp;
    if (elem >= batch) return;

    // Per-lane hidden units: glane + 16*j, j = 0..3 (u < 50 valid).
    float W1a[4], W1b[4], Bh[4], W2a[4], W2b[4];
    #pragma unroll
    for (int j = 0; j < 4; ++j) {
        const int u = glane + 16 * j;
        const bool v = (u < 50);
        W1a[j] = v ? w1[2 * u]     : 0.0f;
        W1b[j] = v ? w1[2 * u + 1] : 0.0f;
        Bh[j]  = v ? b1[u]         : 0.0f;
        W2a[j] = v ? w2[u]         : 0.0f;
        W2b[j] = v ? w2[50 + u]    : 0.0f;
    }
    const float bias0 = b2[0];
    const float bias1 = b2[1];

    float hx = h0[2 * elem];
    float hy = h0[2 * elem + 1];

    if (glane == 0) {
        *reinterpret_cast<float2*>(out + 2 * elem) = make_float2(hx, hy);
    }

    // Vector field: all 16 lanes of the group end with the full (fx, fy).
    auto evalf = [&](float x, float y, float& fx, float& fy) {
        float a0 = 0.0f, a1 = 0.0f;
        #pragma unroll
        for (int j = 0; j < 4; ++j) {
            float z = my_tanh(fmaf(W1a[j], x, fmaf(W1b[j], y, Bh[j])));
            a0 = fmaf(W2a[j], z, a0);
            a1 = fmaf(W2b[j], z, a1);
        }
        #pragma unroll
        for (int off = 8; off; off >>= 1) {
            a0 += __shfl_xor_sync(FULLMASK, a0, off);
            a1 += __shfl_xor_sync(FULLMASK, a1, off);
        }
        fx = a0 + bias0;
        fy = a1 + bias1;
    };

    // Warm-up derivative at t0 (becomes k1 of the first chunk).
    float f0x, f0y;
    evalf(hx, hy, f0x, f0y);

    float tprev = __ldg(&tarr[0]);
    int i0 = 0;                       // current interval start index
    while (i0 < nt - 1) {
        const int c = min(CHUNK, nt - 1 - i0);
        const float tend = __ldg(&tarr[i0 + c]);
        const float H = tend - tprev;
        tprev = tend;

        // RK4 over the whole chunk; k1 = carried f0.
        float k2x, k2y, k3x, k3y, k4x, k4y;
        evalf(fmaf(0.5f * H, f0x, hx), fmaf(0.5f * H, f0y, hy), k2x, k2y);
        evalf(fmaf(0.5f * H, k2x, hx), fmaf(0.5f * H, k2y, hy), k3x, k3y);
        evalf(fmaf(H, k3x, hx),        fmaf(H, k3y, hy),        k4x, k4y);
        const float s = H * (1.0f / 6.0f);
        const float y1x = hx + s * (f0x + 2.0f * (k2x + k3x) + k4x);
        const float y1y = hy + s * (f0y + 2.0f * (k2y + k3y) + k4y);

        // Derivative at chunk end: used for Hermite AND next chunk's k1.
        float f1x, f1y;
        evalf(y1x, y1y, f1x, f1y);

        // Outputs: interior via cubic Hermite, endpoint exact.
        if (glane == 0) {
            const float invc = 1.0f / (float)c;
            for (int j = 1; j < c; ++j) {
                const float th  = j * invc;
                const float om  = 1.0f - th;
                const float h00 = (1.0f + 2.0f * th) * om * om;
                const float h10 = th * om * om;
                const float h01 = th * th * (3.0f - 2.0f * th);
                const float h11 = th * th * (th - 1.0f);
                const float ox = h00 * hx + (h10 * H) * f0x
                               + h01 * y1x + (h11 * H) * f1x;
                const float oy = h00 * hy + (h10 * H) * f0y
                               + h01 * y1y + (h11 * H) * f1y;
                *reinterpret_cast<float2*>(
                    out + (size_t)(i0 + j) * 2 * batch + 2 * elem) =
                    make_float2(ox, oy);
            }
            *reinterpret_cast<float2*>(
                out + (size_t)(i0 + c) * 2 * batch + 2 * elem) =
                make_float2(y1x, y1y);
        }

        hx = y1x; hy = y1y;
        f0x = f1x; f0y = f1y;
        i0 += c;
    }
}

extern "C" void kernel_launch(void* const* d_in, const int* in_sizes, int n_in,
                              void* d_out, int out_size)
{
    const float* h0 = (const float*)d_in[0];
    const float* t  = (const float*)d_in[1];
    const float* w1 = (const float*)d_in[2];
    const float* b1 = (const float*)d_in[3];
    const float* w2 = (const float*)d_in[4];
    const float* b2 = (const float*)d_in[5];
    float* out = (float*)d_out;

    const int batch = in_sizes[0] / 2;   // 1024
    const int nt    = in_sizes[1];       // 100

    const int threads = 128;             // 4 warps = 8 elements per block
    const int elems_per_block = (threads / 32) * 2;
    const int grid = (batch + elems_per_block - 1) / elems_per_block;

    ode_rk4_dense_kernel<<<grid, threads>>>(h0, t, w1, b1, w2, b2, out, nt, batch);
}

// round 4
// speedup vs baseline: 17.4717x; 2.1007x over previous
#include <cuda_runtime.h>

// Neural ODE: dh/dt = W2 @ tanh(W1 @ h + b1) + b2, h in R^2, hidden=50.
//
// Latency-bound problem => minimize sequential critical path:
//  - RK4 with ONE step per 11 output intervals (9 chunks, 37 sequential evals)
//  - interior outputs via cubic Hermite dense output (y0, f0, y1, f1),
//    computed IN PARALLEL across lanes (lane j -> theta = j/c)
//  - f1 reused as next chunk's k1
//  - time array staged in shared memory so no global load sits on the
//    sequential critical path (this was the ~17us intercept in R3)
//
// Error budget: truncation at H=0.0808 was below the 4.4e-7 comparison floor;
// x57 at H=0.222 => ~2e-5. Hermite interp ~1e-6 for this mild field.

#define FULLMASK 0xFFFFFFFFu
#define CHUNK 11
#define MAX_NT 512

// Accurate tanh independent of fast-math flags (~1e-7 rel).
__device__ __forceinline__ float my_tanh(float x) {
    float ax = fabsf(x);
    float e  = __expf(-2.0f * ax);
    float t  = __fdividef(1.0f - e, 1.0f + e);
    return copysignf(t, x);
}

__global__ void __launch_bounds__(128, 8)
ode_rk4_dense_kernel(const float* __restrict__ h0,
                     const float* __restrict__ tarr,
                     const float* __restrict__ w1,   // [50,2]
                     const float* __restrict__ b1,   // [50]
                     const float* __restrict__ w2,   // [2,50]
                     const float* __restrict__ b2,   // [2]
                     float* __restrict__ out,        // [nt, batch, 2]
                     int nt, int batch)
{
    __shared__ float ts[MAX_NT];
    for (int i = threadIdx.x; i < nt && i < MAX_NT; i += blockDim.x)
        ts[i] = tarr[i];
    __syncthreads();

    const int warp  = (blockIdx.x * blockDim.x + threadIdx.x) >> 5;
    const int lane  = threadIdx.x & 31;
    const int grp   = lane >> 4;
    const int glane = lane & 15;
    const int elem  = warp * 2 + grp;
    if (elem >= batch) return;

    // Per-lane hidden units: glane + 16*j, j = 0..3 (u < 50 valid).
    float W1a[4], W1b[4], Bh[4], W2a[4], W2b[4];
    #pragma unroll
    for (int j = 0; j < 4; ++j) {
        const int u = glane + 16 * j;
        const bool v = (u < 50);
        W1a[j] = v ? w1[2 * u]     : 0.0f;
        W1b[j] = v ? w1[2 * u + 1] : 0.0f;
        Bh[j]  = v ? b1[u]         : 0.0f;
        W2a[j] = v ? w2[u]         : 0.0f;
        W2b[j] = v ? w2[50 + u]    : 0.0f;
    }
    const float bias0 = b2[0];
    const float bias1 = b2[1];

    float hx = h0[2 * elem];
    float hy = h0[2 * elem + 1];

    if (glane == 0) {
        *reinterpret_cast<float2*>(out + 2 * elem) = make_float2(hx, hy);
    }

    // Vector field: all 16 lanes of the group end with the full (fx, fy).
    auto evalf = [&](float x, float y, float& fx, float& fy) {
        float a0 = 0.0f, a1 = 0.0f;
        #pragma unroll
        for (int j = 0; j < 4; ++j) {
            float z = my_tanh(fmaf(W1a[j], x, fmaf(W1b[j], y, Bh[j])));
            a0 = fmaf(W2a[j], z, a0);
            a1 = fmaf(W2b[j], z, a1);
        }
        #pragma unroll
        for (int off = 8; off; off >>= 1) {
            a0 += __shfl_xor_sync(FULLMASK, a0, off);
            a1 += __shfl_xor_sync(FULLMASK, a1, off);
        }
        fx = a0 + bias0;
        fy = a1 + bias1;
    };

    // Derivative at t0 (k1 of the first chunk).
    float f0x, f0y;
    evalf(hx, hy, f0x, f0y);

    float tprev = ts[0];
    int i0 = 0;
    while (i0 < nt - 1) {
        const int c = min(CHUNK, nt - 1 - i0);
        const float tend = ts[i0 + c];
        const float H = tend - tprev;
        tprev = tend;

        // RK4 across the whole chunk; k1 = carried f0.
        float k2x, k2y, k3x, k3y, k4x, k4y;
        evalf(fmaf(0.5f * H, f0x, hx), fmaf(0.5f * H, f0y, hy), k2x, k2y);
        evalf(fmaf(0.5f * H, k2x, hx), fmaf(0.5f * H, k2y, hy), k3x, k3y);
        evalf(fmaf(H, k3x, hx),        fmaf(H, k3y, hy),        k4x, k4y);
        const float s = H * (1.0f / 6.0f);
        const float y1x = hx + s * (f0x + 2.0f * (k2x + k3x) + k4x);
        const float y1y = hy + s * (f0y + 2.0f * (k2y + k3y) + k4y);

        // Derivative at chunk end: Hermite slope AND next chunk's k1.
        float f1x, f1y;
        evalf(y1x, y1y, f1x, f1y);

        // Dense output, parallel across lanes:
        // lane j in [1, c) -> interior point theta = j/c; lane 0 -> endpoint.
        if (glane == 0) {
            *reinterpret_cast<float2*>(
                out + (size_t)(i0 + c) * 2 * batch + 2 * elem) =
                make_float2(y1x, y1y);
        } else if (glane < c) {
            const float th  = (float)glane / (float)c;
            const float om  = 1.0f - th;
            const float h00 = (1.0f + 2.0f * th) * om * om;
            const float h10 = th * om * om;
            const float h01 = th * th * (3.0f - 2.0f * th);
            const float h11 = th * th * (th - 1.0f);
            const float ox = h00 * hx + (h10 * H) * f0x
                           + h01 * y1x + (h11 * H) * f1x;
            const float oy = h00 * hy + (h10 * H) * f0y
                           + h01 * y1y + (h11 * H) * f1y;
            *reinterpret_cast<float2*>(
                out + (size_t)(i0 + glane) * 2 * batch + 2 * elem) =
                make_float2(ox, oy);
        }

        hx = y1x; hy = y1y;
        f0x = f1x; f0y = f1y;
        i0 += c;
    }
}

extern "C" void kernel_launch(void* const* d_in, const int* in_sizes, int n_in,
                              void* d_out, int out_size)
{
    const float* h0 = (const float*)d_in[0];
    const float* t  = (const float*)d_in[1];
    const float* w1 = (const float*)d_in[2];
    const float* b1 = (const float*)d_in[3];
    const float* w2 = (const float*)d_in[4];
    const float* b2 = (const float*)d_in[5];
    float* out = (float*)d_out;

    const int batch = in_sizes[0] / 2;   // 1024
    const int nt    = in_sizes[1];       // 100

    const int threads = 128;             // 4 warps = 8 elements per block
    const int elems_per_block = (threads / 32) * 2;
    const int grid = (batch + elems_per_block - 1) / elems_per_block;

    ode_rk4_dense_kernel<<<grid, threads>>>(h0, t, w1, b1, w2, b2, out, nt, batch);
}

// round 5
// speedup vs baseline: 26.2399x; 1.5018x over previous
#include <cuda_runtime.h>

// Neural ODE: dh/dt = W2 @ tanh(W1 @ h + b1) + b2, h in R^2, hidden=50.
//
// Pure sequential-latency problem. This version:
//  - RK4 with ONE step per 33 output intervals (3 chunks, 13 sequential evals)
//  - cubic Hermite dense output for interior points, parallel across lanes
//  - f1 of each chunk reused as k1 of the next
//  - chunk-boundary times prefetched into registers (no smem, no syncthreads,
//    no dependent global load on the critical path)
//  - tanh = 1 - 2*rcp(exp(2x)+1): 2 MUFU ops, ~48cy dependency path,
//    exact saturation at +/-inf, abs err ~1e-7.
//
// Error budget (measured): truncation+interp at H=0.222 was below the 4.4e-7
// comparison floor; x81 at H=0.667 bounds it by ~7e-5 << 1e-3.

#define FULLMASK 0xFFFFFFFFu
#define CHUNK 33
#define MAXB 8   // max chunk boundaries prefetched (covers nt-1 <= 8*CHUNK)

__device__ __forceinline__ float my_tanh(float x) {
    float e = __expf(2.0f * x);                    // FMUL + MUFU.EX2
    return 1.0f - __fdividef(2.0f, e + 1.0f);      // FADD + MUFU.RCP + FMUL + FADD
}

__global__ void __launch_bounds__(128, 8)
ode_rk4_dense_kernel(const float* __restrict__ h0,
                     const float* __restrict__ tarr,
                     const float* __restrict__ w1,   // [50,2]
                     const float* __restrict__ b1,   // [50]
                     const float* __restrict__ w2,   // [2,50]
                     const float* __restrict__ b2,   // [2]
                     float* __restrict__ out,        // [nt, batch, 2]
                     int nt, int batch)
{
    const int warp  = (blockIdx.x * blockDim.x + threadIdx.x) >> 5;
    const int lane  = threadIdx.x & 31;
    const int grp   = lane >> 4;
    const int glane = lane & 15;
    const int elem  = warp * 2 + grp;
    if (elem >= batch) return;

    // Prefetch chunk-boundary times into registers (parallel LDGs, off the
    // sequential path). Boundary k sits at index min(k*CHUNK, nt-1).
    float tb[MAXB + 1];
    #pragma unroll
    for (int k = 0; k <= MAXB; ++k) {
        int idx = k * CHUNK;
        idx = idx < nt - 1 ? idx : nt - 1;
        tb[k] = __ldg(&tarr[idx]);
    }

    // Per-lane hidden units: glane + 16*j, j = 0..3 (u < 50 valid).
    float W1a[4], W1b[4], Bh[4], W2a[4], W2b[4];
    #pragma unroll
    for (int j = 0; j < 4; ++j) {
        const int u = glane + 16 * j;
        const bool v = (u < 50);
        W1a[j] = v ? w1[2 * u]     : 0.0f;
        W1b[j] = v ? w1[2 * u + 1] : 0.0f;
        Bh[j]  = v ? b1[u]         : 0.0f;
        W2a[j] = v ? w2[u]         : 0.0f;
        W2b[j] = v ? w2[50 + u]    : 0.0f;
    }
    const float bias0 = b2[0];
    const float bias1 = b2[1];

    float hx = h0[2 * elem];
    float hy = h0[2 * elem + 1];

    if (glane == 0) {
        *reinterpret_cast<float2*>(out + 2 * elem) = make_float2(hx, hy);
    }

    // Vector field: all 16 lanes of the group end with the full (fx, fy).
    auto evalf = [&](float x, float y, float& fx, float& fy) {
        float a0 = 0.0f, a1 = 0.0f;
        #pragma unroll
        for (int j = 0; j < 4; ++j) {
            float z = my_tanh(fmaf(W1a[j], x, fmaf(W1b[j], y, Bh[j])));
            a0 = fmaf(W2a[j], z, a0);
            a1 = fmaf(W2b[j], z, a1);
        }
        #pragma unroll
        for (int off = 8; off; off >>= 1) {
            a0 += __shfl_xor_sync(FULLMASK, a0, off);
            a1 += __shfl_xor_sync(FULLMASK, a1, off);
        }
        fx = a0 + bias0;
        fy = a1 + bias1;
    };

    // Derivative at t0 (k1 of the first chunk).
    float f0x, f0y;
    evalf(hx, hy, f0x, f0y);

    int i0 = 0;
    int kb = 0;
    while (i0 < nt - 1) {
        const int c = min(CHUNK, nt - 1 - i0);
        const float H = tb[kb + 1] - tb[kb];
        ++kb;

        // RK4 across the whole chunk; k1 = carried f0.
        float k2x, k2y, k3x, k3y, k4x, k4y;
        evalf(fmaf(0.5f * H, f0x, hx), fmaf(0.5f * H, f0y, hy), k2x, k2y);
        evalf(fmaf(0.5f * H, k2x, hx), fmaf(0.5f * H, k2y, hy), k3x, k3y);
        evalf(fmaf(H, k3x, hx),        fmaf(H, k3y, hy),        k4x, k4y);
        const float s = H * (1.0f / 6.0f);
        const float y1x = hx + s * (f0x + 2.0f * (k2x + k3x) + k4x);
        const float y1y = hy + s * (f0y + 2.0f * (k2y + k3y) + k4y);

        // Derivative at chunk end: Hermite slope AND next chunk's k1.
        float f1x, f1y;
        evalf(y1x, y1y, f1x, f1y);

        // Dense output, parallel across lanes: lane g covers theta indices
        // {g, g+16, g+32} within (0, c); lane 0 also stores the endpoint.
        const float invc = 1.0f / (float)c;
        #pragma unroll
        for (int r = 0; r < 3; ++r) {
            const int j = glane + 16 * r;
            if (j >= 1 && j < c) {
                const float th  = (float)j * invc;
                const float om  = 1.0f - th;
                const float h00 = (1.0f + 2.0f * th) * om * om;
                const float h10 = th * om * om;
                const float h01 = th * th * (3.0f - 2.0f * th);
                const float h11 = th * th * (th - 1.0f);
                const float ox = h00 * hx + (h10 * H) * f0x
                               + h01 * y1x + (h11 * H) * f1x;
                const float oy = h00 * hy + (h10 * H) * f0y
                               + h01 * y1y + (h11 * H) * f1y;
                *reinterpret_cast<float2*>(
                    out + (size_t)(i0 + j) * 2 * batch + 2 * elem) =
                    make_float2(ox, oy);
            }
        }
        if (glane == 0) {
            *reinterpret_cast<float2*>(
                out + (size_t)(i0 + c) * 2 * batch + 2 * elem) =
                make_float2(y1x, y1y);
        }

        hx = y1x; hy = y1y;
        f0x = f1x; f0y = f1y;
        i0 += c;
    }
}

extern "C" void kernel_launch(void* const* d_in, const int* in_sizes, int n_in,
                              void* d_out, int out_size)
{
    const float* h0 = (const float*)d_in[0];
    const float* t  = (const float*)d_in[1];
    const float* w1 = (const float*)d_in[2];
    const float* b1 = (const float*)d_in[3];
    const float* w2 = (const float*)d_in[4];
    const float* b2 = (const float*)d_in[5];
    float* out = (float*)d_out;

    const int batch = in_sizes[0] / 2;   // 1024
    const int nt    = in_sizes[1];       // 100

    const int threads = 128;             // 4 warps = 8 elements per block
    const int elems_per_block = (threads / 32) * 2;
    const int grid = (batch + elems_per_block - 1) / elems_per_block;

    ode_rk4_dense_kernel<<<grid, threads>>>(h0, t, w1, b1, w2, b2, out, nt, batch);
}